// round 3
// baseline (speedup 1.0000x reference)
#include <cuda_runtime.h>
#include <cuda_pipeline_primitives.h>

// Spatial GCN (24x24 grid, adj = D^-1 A + I => 5-point stencil) + weight
// + BatchNorm2d(train) + LeakyReLU(0.2), fully fused, one CTA per channel.
//
// R3: float4 node-quad stencil. Thread t owns quad q = t%144 (4 contiguous
// nodes) of plane pq = t/144 within each 4-plane chunk => 16 planes/thread.
// Horizontal neighbors of quad interior are components of the center float4;
// only 2 scalar boundary loads + 2 aligned float4 up/down loads per plane.
// 8-stage cp.async ring (72KB) -> one barrier per chunk. STG.128 stores.

#define GRID_N  24
#define NN      576
#define NQ      144             // float4 quads per plane
#define BATCH   64
#define PPC     4               // planes per chunk
#define NCHUNK  (BATCH / PPC)   // 16
#define NRING   8               // ring stages
#define DEPTH   4               // async depth
#define STAGE_F4 (PPC * NN / 4) // 576
#define BN_EPS  1e-4f
#define SLOPE   0.2f

__global__ __launch_bounds__(NN, 1)
void gcn_bn_lrelu_kernel(const float* __restrict__ x,
                         const float* __restrict__ adj,
                         const float* __restrict__ weight,
                         const float* __restrict__ gamma,
                         const float* __restrict__ beta,
                         float* __restrict__ out,
                         int C)
{
    extern __shared__ float buf[];             // NRING * PPC * NN floats
    __shared__ float red[64];
    __shared__ float s_sb[2];

    const int c  = blockIdx.x;
    const int t  = threadIdx.x;                // 0..575
    const int pq = t / NQ;                     // plane-in-chunk 0..3
    const int q  = t - pq * NQ;                // quad 0..143
    const int row  = q / 6;                    // 0..23
    const int col4 = q - row * 6;              // 0..5 (quad within row)
    const int l0 = 4 * q;                      // first node of quad

    // ---- stencil coefficients (folded with weight) for 4 nodes ----
    float cCw[4], cLw[4], cRw[4], cUw[4], cDw[4];
#pragma unroll
    for (int e = 0; e < 4; ++e) {
        const int l = l0 + e;
        const int j = 4 * col4 + e;            // column 0..23
        const float w = weight[(size_t)c * NN + l];
        cCw[e] = adj[(size_t)l * NN + l] * w;
        cLw[e] = (j > 0)          ? adj[(size_t)(l - 1)      * NN + l] * w : 0.f;
        cRw[e] = (j < GRID_N - 1) ? adj[(size_t)(l + 1)      * NN + l] * w : 0.f;
        cUw[e] = (row > 0)        ? adj[(size_t)(l - GRID_N) * NN + l] * w : 0.f;
        cDw[e] = (row < GRID_N-1) ? adj[(size_t)(l + GRID_N) * NN + l] * w : 0.f;
    }
    // clamped smem offsets (coeff 0 where clamped)
    const int oL = (col4 > 0) ? l0 - 1 : l0;           // scalar left boundary
    const int oR = (col4 < 5) ? l0 + 4 : l0;           // scalar right boundary
    const int qU = (row > 0)  ? q - 6 : q;             // up quad
    const int qD = (row < GRID_N - 1) ? q + 6 : q;     // down quad

    // ---- cp.async: thread t fetches quad q of plane (chunk*4 + pq) ----
    const float4* __restrict__ x4 = (const float4*)x;
    float4* buf4 = (float4*)buf;

#pragma unroll
    for (int s = 0; s < DEPTH; ++s) {
        const float4* src = x4 + ((size_t)((s * PPC + pq) * C + c)) * NQ + q;
        __pipeline_memcpy_async(&buf4[s * STAGE_F4 + t], src, 16);
        __pipeline_commit();
    }

    float4 yv[NCHUNK];
    float4 sum4 = make_float4(0.f, 0.f, 0.f, 0.f);
    float4 sq4  = make_float4(0.f, 0.f, 0.f, 0.f);

#pragma unroll
    for (int ch = 0; ch < NCHUNK; ++ch) {
        __pipeline_wait_prior(DEPTH - 1);
        __syncthreads();
        const int st = ch & (NRING - 1);
        const float*  xb  = buf  + (st * PPC + pq) * NN;
        const float4* xb4 = (const float4*)xb;

        const float4 ctr = xb4[q];
        const float4 up  = xb4[qU];
        const float4 dn  = xb4[qD];
        const float  lft = xb[oL];
        const float  rgt = xb[oR];

        float4 y;
        y.x = cCw[0]*ctr.x; y.x = fmaf(cLw[0], lft,   y.x); y.x = fmaf(cRw[0], ctr.y, y.x);
        y.x = fmaf(cUw[0], up.x, y.x); y.x = fmaf(cDw[0], dn.x, y.x);
        y.y = cCw[1]*ctr.y; y.y = fmaf(cLw[1], ctr.x, y.y); y.y = fmaf(cRw[1], ctr.z, y.y);
        y.y = fmaf(cUw[1], up.y, y.y); y.y = fmaf(cDw[1], dn.y, y.y);
        y.z = cCw[2]*ctr.z; y.z = fmaf(cLw[2], ctr.y, y.z); y.z = fmaf(cRw[2], ctr.w, y.z);
        y.z = fmaf(cUw[2], up.z, y.z); y.z = fmaf(cDw[2], dn.z, y.z);
        y.w = cCw[3]*ctr.w; y.w = fmaf(cLw[3], ctr.z, y.w); y.w = fmaf(cRw[3], rgt,   y.w);
        y.w = fmaf(cUw[3], up.w, y.w); y.w = fmaf(cDw[3], dn.w, y.w);

        yv[ch] = y;
        sum4.x += y.x; sum4.y += y.y; sum4.z += y.z; sum4.w += y.w;
        sq4.x = fmaf(y.x, y.x, sq4.x); sq4.y = fmaf(y.y, y.y, sq4.y);
        sq4.z = fmaf(y.z, y.z, sq4.z); sq4.w = fmaf(y.w, y.w, sq4.w);

        // refill: stage (ch+DEPTH)%NRING was last read at chunk ch-DEPTH,
        // ordered by the entry barriers since then -> no extra barrier.
        const int nc = ch + DEPTH;
        if (nc < NCHUNK) {
            const float4* src = x4 + ((size_t)((nc * PPC + pq) * C + c)) * NQ + q;
            __pipeline_memcpy_async(&buf4[(nc & (NRING - 1)) * STAGE_F4 + t], src, 16);
        }
        __pipeline_commit();
    }

    // ---- block reduction: mean / var ----
    float sum = (sum4.x + sum4.y) + (sum4.z + sum4.w);
    float sq  = (sq4.x  + sq4.y)  + (sq4.z  + sq4.w);
#pragma unroll
    for (int off = 16; off > 0; off >>= 1) {
        sum += __shfl_down_sync(0xffffffffu, sum, off);
        sq  += __shfl_down_sync(0xffffffffu, sq,  off);
    }
    const int warp = t >> 5, lane = t & 31;
    if (lane == 0) { red[warp] = sum; red[32 + warp] = sq; }
    __syncthreads();
    if (t == 0) {
        float s = 0.f, qq = 0.f;
#pragma unroll
        for (int wi = 0; wi < NN / 32; ++wi) { s += red[wi]; qq += red[32 + wi]; }
        const float inv_n = 1.f / (float)(BATCH * NN);
        float mean = s * inv_n;
        float var  = fmaf(qq, inv_n, -mean * mean);
        float rstd = rsqrtf(var + BN_EPS);
        float sc   = gamma[c] * rstd;
        s_sb[0] = sc;
        s_sb[1] = fmaf(-mean, sc, beta[c]);
    }
    __syncthreads();
    const float sc = s_sb[0], bi = s_sb[1];

    // ---- normalize + LeakyReLU + STG.128 stores ----
    float4* __restrict__ out4 = (float4*)out;
#pragma unroll
    for (int ch = 0; ch < NCHUNK; ++ch) {
        const int b = ch * PPC + pq;
        float4 v = yv[ch];
        v.x = fmaf(v.x, sc, bi); v.y = fmaf(v.y, sc, bi);
        v.z = fmaf(v.z, sc, bi); v.w = fmaf(v.w, sc, bi);
        v.x = (v.x >= 0.f) ? v.x : SLOPE * v.x;
        v.y = (v.y >= 0.f) ? v.y : SLOPE * v.y;
        v.z = (v.z >= 0.f) ? v.z : SLOPE * v.z;
        v.w = (v.w >= 0.f) ? v.w : SLOPE * v.w;
        out4[(size_t)(b * C + c) * NQ + q] = v;
    }
}

extern "C" void kernel_launch(void* const* d_in, const int* in_sizes, int n_in,
                              void* d_out, int out_size)
{
    const float* x      = (const float*)d_in[0];
    const float* adj    = (const float*)d_in[1];
    const float* weight = (const float*)d_in[2];
    const float* gamma  = (const float*)d_in[3];
    const float* beta   = (const float*)d_in[4];
    float* out = (float*)d_out;

    const int C = in_sizes[2] / NN;                    // 512
    const size_t smem = (size_t)NRING * PPC * NN * sizeof(float);  // 73728 B

    cudaFuncSetAttribute(gcn_bn_lrelu_kernel,
                         cudaFuncAttributeMaxDynamicSharedMemorySize, (int)smem);
    gcn_bn_lrelu_kernel<<<C, NN, smem>>>(x, adj, weight, gamma, beta, out, C);
}